// round 13
// baseline (speedup 1.0000x reference)
#include <cuda_runtime.h>
#include <cstdint>

#define IN_DIM   64
#define HID_DIM  256
#define OUT_DIM  128
#define TM       256          // items per CTA (32 rows per warp)
#define NTH      256
#define NSM      148

// paired-fragment arrays (uint4 = two adjacent-kt fp16 fragments per lane)
#define W1_QFRAGS (32 * 2 * 32)    // [jt=32][ktp=2][lane]
#define W2_QFRAGS (16 * 8 * 32)    // [nt=16][ktp=8][lane]

__device__ uint4 gW1[W1_QFRAGS];
__device__ uint4 gW2[W2_QFRAGS];
__device__ int g_idx_is_64;

// ---- smem byte offsets --------------------------------------------------
#define SMB_W1     0               // 32 KB
#define SMB_W2     32768           // 64 KB
#define SMB_B1     98304           // 1 KB
#define SMB_B2     99328           // 512 B
#define SMEM_TOTAL 99840

// ---- helpers ------------------------------------------------------------
__device__ __forceinline__ uint32_t pkhf(float lo, float hi) {   // low half = lo
    uint32_t r;
    asm("cvt.rn.f16x2.f32 %0, %1, %2;" : "=r"(r) : "f"(hi), "f"(lo));
    return r;
}
__device__ __forceinline__ void mma_f16(float* c, const uint32_t* a, uint2 b) {
    asm volatile(
        "mma.sync.aligned.m16n8k16.row.col.f32.f16.f16.f32 "
        "{%0,%1,%2,%3}, {%4,%5,%6,%7}, {%8,%9}, {%0,%1,%2,%3};"
        : "+f"(c[0]), "+f"(c[1]), "+f"(c[2]), "+f"(c[3])
        : "r"(a[0]), "r"(a[1]), "r"(a[2]), "r"(a[3]), "r"(b.x), "r"(b.y));
}
__device__ __forceinline__ void red_add2(float* p, float a, float b) {
    asm volatile("red.global.add.v2.f32 [%0], {%1, %2};"
                 :: "l"(p), "f"(a), "f"(b) : "memory");
}
__device__ __forceinline__ void prefetch_l2(const void* p) {
    asm volatile("prefetch.global.L2 [%0];" :: "l"(p));
}

// ---- prep: weights -> paired fp16 fragment layout (+ idx dtype probe) ---
__global__ void prep_weights(const float* __restrict__ W1,
                             const float* __restrict__ W2,
                             const int*   __restrict__ idx32) {
    if (blockIdx.x == 0 && threadIdx.x < 32) {
        int ok = (idx32[2 * threadIdx.x + 1] == 0);
        unsigned m = __ballot_sync(0xffffffffu, ok);
        if (threadIdx.x == 0) g_idx_is_64 = (m == 0xffffffffu);
    }

    int t = blockIdx.x * blockDim.x + threadIdx.x;
    if (t < W1_QFRAGS) {
        // [jt][ktp][lane]: uint4 = frag(kt=2*ktp) ++ frag(kt=2*ktp+1)
        int lane = t & 31, ktp = (t >> 5) & 1, jt = t >> 6;
        int n = jt * 8 + (lane >> 2), tg2 = (lane & 3) * 2;
        int ka = (2 * ktp) * 16 + tg2, kb = (2 * ktp + 1) * 16 + tg2;
        gW1[t] = make_uint4(
            pkhf(W1[ka * HID_DIM + n],       W1[(ka + 1) * HID_DIM + n]),
            pkhf(W1[(ka + 8) * HID_DIM + n], W1[(ka + 9) * HID_DIM + n]),
            pkhf(W1[kb * HID_DIM + n],       W1[(kb + 1) * HID_DIM + n]),
            pkhf(W1[(kb + 8) * HID_DIM + n], W1[(kb + 9) * HID_DIM + n]));
    } else if (t < W1_QFRAGS + W2_QFRAGS) {
        // [nt][ktp][lane]: uint4 = frag(ktg=2*ktp) ++ frag(ktg=2*ktp+1)
        int u = t - W1_QFRAGS;
        int lane = u & 31, ktp = (u >> 5) & 7, nt = u >> 8;
        int n = nt * 8 + (lane >> 2), tg2 = (lane & 3) * 2;
        int ka = (2 * ktp) * 16 + tg2, kb = (2 * ktp + 1) * 16 + tg2;
        gW2[u] = make_uint4(
            pkhf(W2[ka * OUT_DIM + n],       W2[(ka + 1) * OUT_DIM + n]),
            pkhf(W2[(ka + 8) * OUT_DIM + n], W2[(ka + 9) * OUT_DIM + n]),
            pkhf(W2[kb * OUT_DIM + n],       W2[(kb + 1) * OUT_DIM + n]),
            pkhf(W2[(kb + 8) * OUT_DIM + n], W2[(kb + 9) * OUT_DIM + n]));
    }
}

// ---- main persistent fused kernel ---------------------------------------
__global__ __launch_bounds__(NTH, 1)
void item_encoder_mma(const float* __restrict__ x,
                      const int*   __restrict__ idx32,
                      const float* __restrict__ b1,
                      const float* __restrict__ b2,
                      float* __restrict__ out,
                      int n_items, int n_tiles)
{
    extern __shared__ char smc[];
    const uint4* sW1 = (const uint4*)(smc + SMB_W1);
    const uint4* sW2 = (const uint4*)(smc + SMB_W2);
    float* b1s = (float*)(smc + SMB_B1);
    float* b2s = (float*)(smc + SMB_B2);

    const int tid = threadIdx.x;
    const int wid = tid >> 5, lane = tid & 31;
    const int gid = lane >> 2, tig = lane & 3;

    // ---- one-time prologue: stage weights + biases ----------------------
    {
        uint4* d = (uint4*)smc;
        const uint4* s1 = (const uint4*)gW1;
        const uint4* s2 = (const uint4*)gW2;
        #pragma unroll 4
        for (int i = tid; i < 2048; i += NTH) d[i] = s1[i];
        #pragma unroll 4
        for (int i = tid; i < 4096; i += NTH) d[2048 + i] = s2[i];
        b1s[tid] = b1[tid];
        if (tid < TM / 2) b2s[tid] = b2[tid];
    }
    __syncthreads();
    const int is64 = g_idx_is_64;
    const long long stride_items = (long long)gridDim.x * TM;

    // ---- persistent tile loop (no syncs inside) -------------------------
    for (int tile = blockIdx.x; tile < n_tiles; tile += gridDim.x) {
        const long long item0 = (long long)tile * TM;

        // L2 prefetch of next tile's x (two 128B lines per thread)
        {
            long long pfi = item0 + stride_items + (tid >> 1);
            if (pfi < n_items)
                prefetch_l2((const char*)(x + pfi * IN_DIM) + (tid & 1) * 128);
            pfi += 128;
            if (pfi < n_items)
                prefetch_l2((const char*)(x + pfi * IN_DIM) + (tid & 1) * 128);
        }

        // this warp's 4 rows: base + {0, 8, 16, 24}; groups g0={+0,+8}, g1={+16,+24}
        const long long rb = item0 + wid * 32 + gid;
        bool vok[4];
        #pragma unroll
        for (int g = 0; g < 4; ++g) vok[g] = (rb + 8 * g) < n_items;

        // ---- x fp16 A-fragments for both groups -------------------------
        uint32_t xh[2][4][4];
        #pragma unroll
        for (int g2 = 0; g2 < 2; ++g2) {
            const float* p0 = x + (rb + 16 * g2) * IN_DIM + tig * 2;
            const float* p1 = p0 + 8 * IN_DIM;
            #pragma unroll
            for (int kt = 0; kt < 4; ++kt) {
                float2 f0 = make_float2(0.f, 0.f), f1 = f0, f2 = f0, f3 = f0;
                if (vok[2 * g2])     { f0 = *(const float2*)(p0 + kt * 16);
                                       f2 = *(const float2*)(p0 + kt * 16 + 8); }
                if (vok[2 * g2 + 1]) { f1 = *(const float2*)(p1 + kt * 16);
                                       f3 = *(const float2*)(p1 + kt * 16 + 8); }
                xh[g2][kt][0] = pkhf(f0.x, f0.y);
                xh[g2][kt][1] = pkhf(f1.x, f1.y);
                xh[g2][kt][2] = pkhf(f2.x, f2.y);
                xh[g2][kt][3] = pkhf(f3.x, f3.y);
            }
        }
        // bins (direct gmem loads)
        int bins[4];
        #pragma unroll
        for (int g = 0; g < 4; ++g) {
            long long rr = rb + 8 * g;
            bins[g] = vok[g] ? (is64 ? (int)((const long long*)idx32)[rr]
                                     : idx32[rr])
                             : -1;
        }

        float o[2][16][4];
        #pragma unroll
        for (int g2 = 0; g2 < 2; ++g2)
            #pragma unroll
            for (int nt = 0; nt < 16; ++nt)
                #pragma unroll
                for (int q = 0; q < 4; ++q) o[g2][nt][q] = 0.f;

        // ---- 4 hidden chunks of 64 --------------------------------------
        #pragma unroll 1
        for (int c = 0; c < 4; ++c) {
            // GEMM1: both groups share each W1 fragment pair (R12 structure)
            uint32_t ah[2][4][4];
            #pragma unroll
            for (int j = 0; j < 8; ++j) {
                int fb = (c * 8 + j) * 2 * 32 + lane;
                uint4 qa = sW1[fb], qb = sW1[fb + 32];
                uint2 w0 = make_uint2(qa.x, qa.y), w1f = make_uint2(qa.z, qa.w);
                uint2 w2f = make_uint2(qb.x, qb.y), w3f = make_uint2(qb.z, qb.w);
                float2 bb = *(const float2*)&b1s[c * 64 + j * 8 + tig * 2];
                int kt = j >> 1, s = (j & 1) * 2;
                #pragma unroll
                for (int g2 = 0; g2 < 2; ++g2) {
                    float cc[4] = {0.f, 0.f, 0.f, 0.f};
                    mma_f16(cc, xh[g2][0], w0);
                    mma_f16(cc, xh[g2][1], w1f);
                    mma_f16(cc, xh[g2][2], w2f);
                    mma_f16(cc, xh[g2][3], w3f);
                    ah[g2][kt][s]     = pkhf(fmaxf(cc[0] + bb.x, 0.f),
                                             fmaxf(cc[1] + bb.y, 0.f));
                    ah[g2][kt][s + 1] = pkhf(fmaxf(cc[2] + bb.x, 0.f),
                                             fmaxf(cc[3] + bb.y, 0.f));
                }
            }

            // GEMM2: nt-pair interleave -> 4 independent accumulator chains,
            // dependent same-accumulator mmas separated by 3 issues.
            #pragma unroll
            for (int ntp = 0; ntp < 8; ++ntp) {
                int ntA = 2 * ntp, ntB = ntA + 1;
                int fbA = (ntA * 8 + c * 2) * 32 + lane;
                int fbB = (ntB * 8 + c * 2) * 32 + lane;
                uint4 qa = sW2[fbA], qb = sW2[fbA + 32];
                uint4 qc = sW2[fbB], qd = sW2[fbB + 32];
                uint2 a0 = make_uint2(qa.x, qa.y), a1 = make_uint2(qa.z, qa.w);
                uint2 a2 = make_uint2(qb.x, qb.y), a3 = make_uint2(qb.z, qb.w);
                uint2 c0 = make_uint2(qc.x, qc.y), c1f = make_uint2(qc.z, qc.w);
                uint2 c2 = make_uint2(qd.x, qd.y), c3 = make_uint2(qd.z, qd.w);

                mma_f16(o[0][ntA], ah[0][0], a0);
                mma_f16(o[1][ntA], ah[1][0], a0);
                mma_f16(o[0][ntB], ah[0][0], c0);
                mma_f16(o[1][ntB], ah[1][0], c0);

                mma_f16(o[0][ntA], ah[0][1], a1);
                mma_f16(o[1][ntA], ah[1][1], a1);
                mma_f16(o[0][ntB], ah[0][1], c1f);
                mma_f16(o[1][ntB], ah[1][1], c1f);

                mma_f16(o[0][ntA], ah[0][2], a2);
                mma_f16(o[1][ntA], ah[1][2], a2);
                mma_f16(o[0][ntB], ah[0][2], c2);
                mma_f16(o[1][ntB], ah[1][2], c2);

                mma_f16(o[0][ntA], ah[0][3], a3);
                mma_f16(o[1][ntA], ah[1][3], a3);
                mma_f16(o[0][ntB], ah[0][3], c3);
                mma_f16(o[1][ntB], ah[1][3], c3);
            }
        }

        // ---- epilogue: +b2, scatter-add (4 rows) ------------------------
        #pragma unroll
        for (int nt = 0; nt < 16; ++nt) {
            int col = nt * 8 + tig * 2;
            float2 bb = *(const float2*)&b2s[col];
            #pragma unroll
            for (int g2 = 0; g2 < 2; ++g2) {
                if (bins[2 * g2] >= 0)
                    red_add2(out + (size_t)bins[2 * g2] * OUT_DIM + col,
                             o[g2][nt][0] + bb.x, o[g2][nt][1] + bb.y);
                if (bins[2 * g2 + 1] >= 0)
                    red_add2(out + (size_t)bins[2 * g2 + 1] * OUT_DIM + col,
                             o[g2][nt][2] + bb.x, o[g2][nt][3] + bb.y);
            }
        }
    }
}

extern "C" void kernel_launch(void* const* d_in, const int* in_sizes, int n_in,
                              void* d_out, int out_size)
{
    const float* x     = (const float*)d_in[0];
    const int*   idx32 = (const int*)d_in[1];
    int wbase = 3;
    if (n_in >= 3 && in_sizes[2] == IN_DIM * HID_DIM) wbase = 2;
    const float* W1 = (const float*)d_in[wbase + 0];
    const float* b1 = (const float*)d_in[wbase + 1];
    const float* W2 = (const float*)d_in[wbase + 2];
    const float* b2 = (const float*)d_in[wbase + 3];
    float* out = (float*)d_out;

    const int n_items = in_sizes[0] / IN_DIM;
    const int n_tiles = (n_items + TM - 1) / TM;

    cudaFuncSetAttribute(item_encoder_mma,
                         cudaFuncAttributeMaxDynamicSharedMemorySize, SMEM_TOTAL);

    cudaMemsetAsync(d_out, 0, (size_t)out_size * sizeof(float), (cudaStream_t)0);

    const int prep_items = W1_QFRAGS + W2_QFRAGS;   // 6144
    prep_weights<<<prep_items / NTH, NTH, 0, (cudaStream_t)0>>>(W1, W2, idx32);

    item_encoder_mma<<<NSM, NTH, SMEM_TOTAL, (cudaStream_t)0>>>(
        x, idx32, b1, b2, out, n_items, n_tiles);
}

// round 14
// speedup vs baseline: 1.0019x; 1.0019x over previous
#include <cuda_runtime.h>
#include <cstdint>

#define IN_DIM   64
#define HID_DIM  256
#define OUT_DIM  128
#define TM       256          // items per CTA (32 rows per warp)
#define NTH      256
#define NSM      148

// paired-fragment arrays (uint4 = two adjacent-kt fp16 fragments per lane)
#define W1_QFRAGS (32 * 2 * 32)    // [jt=32][ktp=2][lane]
#define W2_QFRAGS (16 * 8 * 32)    // [nt=16][ktp=8][lane]

__device__ uint4 gW1[W1_QFRAGS];
__device__ uint4 gW2[W2_QFRAGS];
__device__ int g_idx_is_64;

// ---- smem byte offsets --------------------------------------------------
#define SMB_W1     0               // 32 KB
#define SMB_W2     32768           // 64 KB
#define SMB_B1     98304           // 1 KB
#define SMB_B2     99328           // 512 B
#define SMEM_TOTAL 99840

// ---- helpers ------------------------------------------------------------
__device__ __forceinline__ uint32_t pkhf(float lo, float hi) {   // low half = lo
    uint32_t r;
    asm("cvt.rn.f16x2.f32 %0, %1, %2;" : "=r"(r) : "f"(hi), "f"(lo));
    return r;
}
// NOTE: intentionally NOT volatile — no side effects, lets ptxas schedule
// mmas against LDS and across the GEMM1/GEMM2 seam.
__device__ __forceinline__ void mma_f16(float* c, const uint32_t* a, uint2 b) {
    asm("mma.sync.aligned.m16n8k16.row.col.f32.f16.f16.f32 "
        "{%0,%1,%2,%3}, {%4,%5,%6,%7}, {%8,%9}, {%0,%1,%2,%3};"
        : "+f"(c[0]), "+f"(c[1]), "+f"(c[2]), "+f"(c[3])
        : "r"(a[0]), "r"(a[1]), "r"(a[2]), "r"(a[3]), "r"(b.x), "r"(b.y));
}
__device__ __forceinline__ void red_add2(float* p, float a, float b) {
    asm volatile("red.global.add.v2.f32 [%0], {%1, %2};"
                 :: "l"(p), "f"(a), "f"(b) : "memory");
}
__device__ __forceinline__ void prefetch_l2(const void* p) {
    asm volatile("prefetch.global.L2 [%0];" :: "l"(p));
}

// ---- prep: weights -> paired fp16 fragment layout (+ idx dtype probe) ---
__global__ void prep_weights(const float* __restrict__ W1,
                             const float* __restrict__ W2,
                             const int*   __restrict__ idx32) {
    if (blockIdx.x == 0 && threadIdx.x < 32) {
        int ok = (idx32[2 * threadIdx.x + 1] == 0);
        unsigned m = __ballot_sync(0xffffffffu, ok);
        if (threadIdx.x == 0) g_idx_is_64 = (m == 0xffffffffu);
    }

    int t = blockIdx.x * blockDim.x + threadIdx.x;
    if (t < W1_QFRAGS) {
        // [jt][ktp][lane]: uint4 = frag(kt=2*ktp) ++ frag(kt=2*ktp+1)
        int lane = t & 31, ktp = (t >> 5) & 1, jt = t >> 6;
        int n = jt * 8 + (lane >> 2), tg2 = (lane & 3) * 2;
        int ka = (2 * ktp) * 16 + tg2, kb = (2 * ktp + 1) * 16 + tg2;
        gW1[t] = make_uint4(
            pkhf(W1[ka * HID_DIM + n],       W1[(ka + 1) * HID_DIM + n]),
            pkhf(W1[(ka + 8) * HID_DIM + n], W1[(ka + 9) * HID_DIM + n]),
            pkhf(W1[kb * HID_DIM + n],       W1[(kb + 1) * HID_DIM + n]),
            pkhf(W1[(kb + 8) * HID_DIM + n], W1[(kb + 9) * HID_DIM + n]));
    } else if (t < W1_QFRAGS + W2_QFRAGS) {
        // [nt][ktp][lane]: uint4 = frag(ktg=2*ktp) ++ frag(ktg=2*ktp+1)
        int u = t - W1_QFRAGS;
        int lane = u & 31, ktp = (u >> 5) & 7, nt = u >> 8;
        int n = nt * 8 + (lane >> 2), tg2 = (lane & 3) * 2;
        int ka = (2 * ktp) * 16 + tg2, kb = (2 * ktp + 1) * 16 + tg2;
        gW2[u] = make_uint4(
            pkhf(W2[ka * OUT_DIM + n],       W2[(ka + 1) * OUT_DIM + n]),
            pkhf(W2[(ka + 8) * OUT_DIM + n], W2[(ka + 9) * OUT_DIM + n]),
            pkhf(W2[kb * OUT_DIM + n],       W2[(kb + 1) * OUT_DIM + n]),
            pkhf(W2[(kb + 8) * OUT_DIM + n], W2[(kb + 9) * OUT_DIM + n]));
    }
}

// ---- main persistent fused kernel ---------------------------------------
__global__ __launch_bounds__(NTH, 1)
void item_encoder_mma(const float* __restrict__ x,
                      const int*   __restrict__ idx32,
                      const float* __restrict__ b1,
                      const float* __restrict__ b2,
                      float* __restrict__ out,
                      int n_items, int n_tiles)
{
    extern __shared__ char smc[];
    const uint4* sW1 = (const uint4*)(smc + SMB_W1);
    const uint4* sW2 = (const uint4*)(smc + SMB_W2);
    float* b1s = (float*)(smc + SMB_B1);
    float* b2s = (float*)(smc + SMB_B2);

    const int tid = threadIdx.x;
    const int wid = tid >> 5, lane = tid & 31;
    const int gid = lane >> 2, tig = lane & 3;

    // ---- one-time prologue: stage weights + biases ----------------------
    {
        uint4* d = (uint4*)smc;
        const uint4* s1 = (const uint4*)gW1;
        const uint4* s2 = (const uint4*)gW2;
        #pragma unroll 4
        for (int i = tid; i < 2048; i += NTH) d[i] = s1[i];
        #pragma unroll 4
        for (int i = tid; i < 4096; i += NTH) d[2048 + i] = s2[i];
        b1s[tid] = b1[tid];
        if (tid < TM / 2) b2s[tid] = b2[tid];
    }
    __syncthreads();
    const int is64 = g_idx_is_64;
    const long long stride_items = (long long)gridDim.x * TM;

    // ---- persistent tile loop (no syncs inside) -------------------------
    for (int tile = blockIdx.x; tile < n_tiles; tile += gridDim.x) {
        const long long item0 = (long long)tile * TM;

        // L2 prefetch of next tile's x (two 128B lines per thread)
        {
            long long pfi = item0 + stride_items + (tid >> 1);
            if (pfi < n_items)
                prefetch_l2((const char*)(x + pfi * IN_DIM) + (tid & 1) * 128);
            pfi += 128;
            if (pfi < n_items)
                prefetch_l2((const char*)(x + pfi * IN_DIM) + (tid & 1) * 128);
        }

        // this warp's 4 rows: base + {0, 8, 16, 24}; groups g0={+0,+8}, g1={+16,+24}
        const long long rb = item0 + wid * 32 + gid;
        bool vok[4];
        #pragma unroll
        for (int g = 0; g < 4; ++g) vok[g] = (rb + 8 * g) < n_items;

        // ---- x fp16 A-fragments for both groups -------------------------
        uint32_t xh[2][4][4];
        #pragma unroll
        for (int g2 = 0; g2 < 2; ++g2) {
            const float* p0 = x + (rb + 16 * g2) * IN_DIM + tig * 2;
            const float* p1 = p0 + 8 * IN_DIM;
            #pragma unroll
            for (int kt = 0; kt < 4; ++kt) {
                float2 f0 = make_float2(0.f, 0.f), f1 = f0, f2 = f0, f3 = f0;
                if (vok[2 * g2])     { f0 = *(const float2*)(p0 + kt * 16);
                                       f2 = *(const float2*)(p0 + kt * 16 + 8); }
                if (vok[2 * g2 + 1]) { f1 = *(const float2*)(p1 + kt * 16);
                                       f3 = *(const float2*)(p1 + kt * 16 + 8); }
                xh[g2][kt][0] = pkhf(f0.x, f0.y);
                xh[g2][kt][1] = pkhf(f1.x, f1.y);
                xh[g2][kt][2] = pkhf(f2.x, f2.y);
                xh[g2][kt][3] = pkhf(f3.x, f3.y);
            }
        }
        // bins (direct gmem loads)
        int bins[4];
        #pragma unroll
        for (int g = 0; g < 4; ++g) {
            long long rr = rb + 8 * g;
            bins[g] = vok[g] ? (is64 ? (int)((const long long*)idx32)[rr]
                                     : idx32[rr])
                             : -1;
        }

        float o[2][16][4];
        #pragma unroll
        for (int g2 = 0; g2 < 2; ++g2)
            #pragma unroll
            for (int nt = 0; nt < 16; ++nt)
                #pragma unroll
                for (int q = 0; q < 4; ++q) o[g2][nt][q] = 0.f;

        // ---- 4 hidden chunks of 64 --------------------------------------
        #pragma unroll 1
        for (int c = 0; c < 4; ++c) {
            // GEMM1: g2-interleaved chains (dependency distance 2)
            uint32_t ah[2][4][4];
            #pragma unroll
            for (int j = 0; j < 8; ++j) {
                int fb = (c * 8 + j) * 2 * 32 + lane;
                uint4 qa = sW1[fb], qb = sW1[fb + 32];
                uint2 w0 = make_uint2(qa.x, qa.y), w1f = make_uint2(qa.z, qa.w);
                uint2 w2f = make_uint2(qb.x, qb.y), w3f = make_uint2(qb.z, qb.w);
                float2 bb = *(const float2*)&b1s[c * 64 + j * 8 + tig * 2];
                int kt = j >> 1, s = (j & 1) * 2;

                float cc0[4] = {0.f, 0.f, 0.f, 0.f};
                float cc1[4] = {0.f, 0.f, 0.f, 0.f};
                mma_f16(cc0, xh[0][0], w0);
                mma_f16(cc1, xh[1][0], w0);
                mma_f16(cc0, xh[0][1], w1f);
                mma_f16(cc1, xh[1][1], w1f);
                mma_f16(cc0, xh[0][2], w2f);
                mma_f16(cc1, xh[1][2], w2f);
                mma_f16(cc0, xh[0][3], w3f);
                mma_f16(cc1, xh[1][3], w3f);

                ah[0][kt][s]     = pkhf(fmaxf(cc0[0] + bb.x, 0.f),
                                        fmaxf(cc0[1] + bb.y, 0.f));
                ah[0][kt][s + 1] = pkhf(fmaxf(cc0[2] + bb.x, 0.f),
                                        fmaxf(cc0[3] + bb.y, 0.f));
                ah[1][kt][s]     = pkhf(fmaxf(cc1[0] + bb.x, 0.f),
                                        fmaxf(cc1[1] + bb.y, 0.f));
                ah[1][kt][s + 1] = pkhf(fmaxf(cc1[2] + bb.x, 0.f),
                                        fmaxf(cc1[3] + bb.y, 0.f));
            }

            // GEMM2: each W2 fragment pair feeds both groups (R12 form)
            #pragma unroll
            for (int nt = 0; nt < 16; ++nt) {
                int fb = (nt * 8 + c * 2) * 32 + lane;
                uint4 qa = sW2[fb], qb = sW2[fb + 32];
                uint2 b0 = make_uint2(qa.x, qa.y), b1f = make_uint2(qa.z, qa.w);
                uint2 b2f = make_uint2(qb.x, qb.y), b3f = make_uint2(qb.z, qb.w);
                mma_f16(o[0][nt], ah[0][0], b0);
                mma_f16(o[1][nt], ah[1][0], b0);
                mma_f16(o[0][nt], ah[0][1], b1f);
                mma_f16(o[1][nt], ah[1][1], b1f);
                mma_f16(o[0][nt], ah[0][2], b2f);
                mma_f16(o[1][nt], ah[1][2], b2f);
                mma_f16(o[0][nt], ah[0][3], b3f);
                mma_f16(o[1][nt], ah[1][3], b3f);
            }
        }

        // ---- epilogue: +b2, scatter-add (4 rows) ------------------------
        #pragma unroll
        for (int nt = 0; nt < 16; ++nt) {
            int col = nt * 8 + tig * 2;
            float2 bb = *(const float2*)&b2s[col];
            #pragma unroll
            for (int g2 = 0; g2 < 2; ++g2) {
                if (bins[2 * g2] >= 0)
                    red_add2(out + (size_t)bins[2 * g2] * OUT_DIM + col,
                             o[g2][nt][0] + bb.x, o[g2][nt][1] + bb.y);
                if (bins[2 * g2 + 1] >= 0)
                    red_add2(out + (size_t)bins[2 * g2 + 1] * OUT_DIM + col,
                             o[g2][nt][2] + bb.x, o[g2][nt][3] + bb.y);
            }
        }
    }
}

extern "C" void kernel_launch(void* const* d_in, const int* in_sizes, int n_in,
                              void* d_out, int out_size)
{
    const float* x     = (const float*)d_in[0];
    const int*   idx32 = (const int*)d_in[1];
    int wbase = 3;
    if (n_in >= 3 && in_sizes[2] == IN_DIM * HID_DIM) wbase = 2;
    const float* W1 = (const float*)d_in[wbase + 0];
    const float* b1 = (const float*)d_in[wbase + 1];
    const float* W2 = (const float*)d_in[wbase + 2];
    const float* b2 = (const float*)d_in[wbase + 3];
    float* out = (float*)d_out;

    const int n_items = in_sizes[0] / IN_DIM;
    const int n_tiles = (n_items + TM - 1) / TM;

    cudaFuncSetAttribute(item_encoder_mma,
                         cudaFuncAttributeMaxDynamicSharedMemorySize, SMEM_TOTAL);

    cudaMemsetAsync(d_out, 0, (size_t)out_size * sizeof(float), (cudaStream_t)0);

    const int prep_items = W1_QFRAGS + W2_QFRAGS;   // 6144
    prep_weights<<<prep_items / NTH, NTH, 0, (cudaStream_t)0>>>(W1, W2, idx32);

    item_encoder_mma<<<NSM, NTH, SMEM_TOTAL, (cudaStream_t)0>>>(
        x, idx32, b1, b2, out, n_items, n_tiles);
}

// round 15
// speedup vs baseline: 1.0878x; 1.0857x over previous
#include <cuda_runtime.h>
#include <cstdint>

#define IN_DIM   64
#define HID_DIM  256
#define OUT_DIM  128
#define TM       256          // items per CTA (32 rows per warp)
#define NTH      256
#define NSM      148

// paired-fragment arrays (uint4 = two adjacent-kt fp16 fragments per lane)
#define W1_QFRAGS (32 * 2 * 32)    // [jt=32][ktp=2][lane]
#define W2_QFRAGS (16 * 8 * 32)    // [nt=16][ktp=8][lane]

__device__ uint4 gW1[W1_QFRAGS];
__device__ uint4 gW2[W2_QFRAGS];
__device__ int g_idx_is_64;

// ---- smem byte offsets --------------------------------------------------
#define SMB_W1     0               // 32 KB
#define SMB_W2     32768           // 64 KB
#define SMB_B1     98304           // 1 KB
#define SMB_B2     99328           // 512 B
#define SMEM_TOTAL 99840

// ---- helpers ------------------------------------------------------------
__device__ __forceinline__ uint32_t pkhf(float lo, float hi) {   // low half = lo
    uint32_t r;
    asm("cvt.rn.f16x2.f32 %0, %1, %2;" : "=r"(r) : "f"(hi), "f"(lo));
    return r;
}
// NOTE: intentionally NOT volatile — lets ptxas schedule mmas freely.
__device__ __forceinline__ void mma_f16(float* c, const uint32_t* a, uint2 b) {
    asm("mma.sync.aligned.m16n8k16.row.col.f32.f16.f16.f32 "
        "{%0,%1,%2,%3}, {%4,%5,%6,%7}, {%8,%9}, {%0,%1,%2,%3};"
        : "+f"(c[0]), "+f"(c[1]), "+f"(c[2]), "+f"(c[3])
        : "r"(a[0]), "r"(a[1]), "r"(a[2]), "r"(a[3]), "r"(b.x), "r"(b.y));
}
__device__ __forceinline__ void red_add4(float* p, float a, float b, float c, float d) {
    asm volatile("red.global.add.v4.f32 [%0], {%1, %2, %3, %4};"
                 :: "l"(p), "f"(a), "f"(b), "f"(c), "f"(d) : "memory");
}
__device__ __forceinline__ void prefetch_l2(const void* p) {
    asm volatile("prefetch.global.L2 [%0];" :: "l"(p));
}

// Output-column permutation for W2 fragments:
// block nt = 2m+s, intra-block col j (0..7)  ->  physical col
//   sigma(nt, j) = 16*m + 4*(j>>1) + 2*s + (j&1)
// With this, thread tig's pairs from blocks (2m, 2m+1) cover physical cols
// [16m + 4*tig, 16m + 4*tig + 4)  ->  one red.add.v4 per (m, row).

// ---- prep: weights -> paired fp16 fragment layout (+ idx dtype probe) ---
__global__ void prep_weights(const float* __restrict__ W1,
                             const float* __restrict__ W2,
                             const int*   __restrict__ idx32) {
    if (blockIdx.x == 0 && threadIdx.x < 32) {
        int ok = (idx32[2 * threadIdx.x + 1] == 0);
        unsigned m = __ballot_sync(0xffffffffu, ok);
        if (threadIdx.x == 0) g_idx_is_64 = (m == 0xffffffffu);
    }

    int t = blockIdx.x * blockDim.x + threadIdx.x;
    if (t < W1_QFRAGS) {
        // [jt][ktp][lane]: uint4 = frag(kt=2*ktp) ++ frag(kt=2*ktp+1)
        int lane = t & 31, ktp = (t >> 5) & 1, jt = t >> 6;
        int n = jt * 8 + (lane >> 2), tg2 = (lane & 3) * 2;
        int ka = (2 * ktp) * 16 + tg2, kb = (2 * ktp + 1) * 16 + tg2;
        gW1[t] = make_uint4(
            pkhf(W1[ka * HID_DIM + n],       W1[(ka + 1) * HID_DIM + n]),
            pkhf(W1[(ka + 8) * HID_DIM + n], W1[(ka + 9) * HID_DIM + n]),
            pkhf(W1[kb * HID_DIM + n],       W1[(kb + 1) * HID_DIM + n]),
            pkhf(W1[(kb + 8) * HID_DIM + n], W1[(kb + 9) * HID_DIM + n]));
    } else if (t < W1_QFRAGS + W2_QFRAGS) {
        // [nt][ktp][lane], n permuted by sigma (see above)
        int u = t - W1_QFRAGS;
        int lane = u & 31, ktp = (u >> 5) & 7, nt = u >> 8;
        int j = lane >> 2;                       // intra-block col
        int m = nt >> 1, s = nt & 1;
        int n = 16 * m + 4 * (j >> 1) + 2 * s + (j & 1);
        int tg2 = (lane & 3) * 2;
        int ka = (2 * ktp) * 16 + tg2, kb = (2 * ktp + 1) * 16 + tg2;
        gW2[u] = make_uint4(
            pkhf(W2[ka * OUT_DIM + n],       W2[(ka + 1) * OUT_DIM + n]),
            pkhf(W2[(ka + 8) * OUT_DIM + n], W2[(ka + 9) * OUT_DIM + n]),
            pkhf(W2[kb * OUT_DIM + n],       W2[(kb + 1) * OUT_DIM + n]),
            pkhf(W2[(kb + 8) * OUT_DIM + n], W2[(kb + 9) * OUT_DIM + n]));
    }
}

// ---- main persistent fused kernel ---------------------------------------
__global__ __launch_bounds__(NTH, 1)
void item_encoder_mma(const float* __restrict__ x,
                      const int*   __restrict__ idx32,
                      const float* __restrict__ b1,
                      const float* __restrict__ b2,
                      float* __restrict__ out,
                      int n_items, int n_tiles)
{
    extern __shared__ char smc[];
    const uint4* sW1 = (const uint4*)(smc + SMB_W1);
    const uint4* sW2 = (const uint4*)(smc + SMB_W2);
    float* b1s = (float*)(smc + SMB_B1);
    float* b2s = (float*)(smc + SMB_B2);

    const int tid = threadIdx.x;
    const int wid = tid >> 5, lane = tid & 31;
    const int gid = lane >> 2, tig = lane & 3;

    // ---- one-time prologue: stage weights + biases ----------------------
    {
        uint4* d = (uint4*)smc;
        const uint4* s1 = (const uint4*)gW1;
        const uint4* s2 = (const uint4*)gW2;
        #pragma unroll 4
        for (int i = tid; i < 2048; i += NTH) d[i] = s1[i];
        #pragma unroll 4
        for (int i = tid; i < 4096; i += NTH) d[2048 + i] = s2[i];
        b1s[tid] = b1[tid];
        if (tid < TM / 2) b2s[tid] = b2[tid];
    }
    __syncthreads();
    const int is64 = g_idx_is_64;
    const long long stride_items = (long long)gridDim.x * TM;

    // ---- persistent tile loop (no syncs inside) -------------------------
    for (int tile = blockIdx.x; tile < n_tiles; tile += gridDim.x) {
        const long long item0 = (long long)tile * TM;

        // L2 prefetch of next tile's x (two 128B lines per thread)
        {
            long long pfi = item0 + stride_items + (tid >> 1);
            if (pfi < n_items)
                prefetch_l2((const char*)(x + pfi * IN_DIM) + (tid & 1) * 128);
            pfi += 128;
            if (pfi < n_items)
                prefetch_l2((const char*)(x + pfi * IN_DIM) + (tid & 1) * 128);
        }

        // this warp's 4 rows: base + {0, 8, 16, 24}; groups g0={+0,+8}, g1={+16,+24}
        const long long rb = item0 + wid * 32 + gid;
        bool vok[4];
        #pragma unroll
        for (int g = 0; g < 4; ++g) vok[g] = (rb + 8 * g) < n_items;

        // ---- x fp16 A-fragments for both groups -------------------------
        uint32_t xh[2][4][4];
        #pragma unroll
        for (int g2 = 0; g2 < 2; ++g2) {
            const float* p0 = x + (rb + 16 * g2) * IN_DIM + tig * 2;
            const float* p1 = p0 + 8 * IN_DIM;
            #pragma unroll
            for (int kt = 0; kt < 4; ++kt) {
                float2 f0 = make_float2(0.f, 0.f), f1 = f0, f2 = f0, f3 = f0;
                if (vok[2 * g2])     { f0 = *(const float2*)(p0 + kt * 16);
                                       f2 = *(const float2*)(p0 + kt * 16 + 8); }
                if (vok[2 * g2 + 1]) { f1 = *(const float2*)(p1 + kt * 16);
                                       f3 = *(const float2*)(p1 + kt * 16 + 8); }
                xh[g2][kt][0] = pkhf(f0.x, f0.y);
                xh[g2][kt][1] = pkhf(f1.x, f1.y);
                xh[g2][kt][2] = pkhf(f2.x, f2.y);
                xh[g2][kt][3] = pkhf(f3.x, f3.y);
            }
        }
        // bins (direct gmem loads)
        int bins[4];
        #pragma unroll
        for (int g = 0; g < 4; ++g) {
            long long rr = rb + 8 * g;
            bins[g] = vok[g] ? (is64 ? (int)((const long long*)idx32)[rr]
                                     : idx32[rr])
                             : -1;
        }

        float o[2][16][4];
        #pragma unroll
        for (int g2 = 0; g2 < 2; ++g2)
            #pragma unroll
            for (int nt = 0; nt < 16; ++nt)
                #pragma unroll
                for (int q = 0; q < 4; ++q) o[g2][nt][q] = 0.f;

        // ---- 4 hidden chunks of 64 --------------------------------------
        #pragma unroll 1
        for (int c = 0; c < 4; ++c) {
            // GEMM1: g2-interleaved chains (dependency distance 2)
            uint32_t ah[2][4][4];
            #pragma unroll
            for (int j = 0; j < 8; ++j) {
                int fb = (c * 8 + j) * 2 * 32 + lane;
                uint4 qa = sW1[fb], qb = sW1[fb + 32];
                uint2 w0 = make_uint2(qa.x, qa.y), w1f = make_uint2(qa.z, qa.w);
                uint2 w2f = make_uint2(qb.x, qb.y), w3f = make_uint2(qb.z, qb.w);
                float2 bb = *(const float2*)&b1s[c * 64 + j * 8 + tig * 2];
                int kt = j >> 1, s = (j & 1) * 2;

                float cc0[4] = {0.f, 0.f, 0.f, 0.f};
                float cc1[4] = {0.f, 0.f, 0.f, 0.f};
                mma_f16(cc0, xh[0][0], w0);
                mma_f16(cc1, xh[1][0], w0);
                mma_f16(cc0, xh[0][1], w1f);
                mma_f16(cc1, xh[1][1], w1f);
                mma_f16(cc0, xh[0][2], w2f);
                mma_f16(cc1, xh[1][2], w2f);
                mma_f16(cc0, xh[0][3], w3f);
                mma_f16(cc1, xh[1][3], w3f);

                ah[0][kt][s]     = pkhf(fmaxf(cc0[0] + bb.x, 0.f),
                                        fmaxf(cc0[1] + bb.y, 0.f));
                ah[0][kt][s + 1] = pkhf(fmaxf(cc0[2] + bb.x, 0.f),
                                        fmaxf(cc0[3] + bb.y, 0.f));
                ah[1][kt][s]     = pkhf(fmaxf(cc1[0] + bb.x, 0.f),
                                        fmaxf(cc1[1] + bb.y, 0.f));
                ah[1][kt][s + 1] = pkhf(fmaxf(cc1[2] + bb.x, 0.f),
                                        fmaxf(cc1[3] + bb.y, 0.f));
            }

            // GEMM2: each W2 fragment pair feeds both groups
            #pragma unroll
            for (int nt = 0; nt < 16; ++nt) {
                int fb = (nt * 8 + c * 2) * 32 + lane;
                uint4 qa = sW2[fb], qb = sW2[fb + 32];
                uint2 b0 = make_uint2(qa.x, qa.y), b1f = make_uint2(qa.z, qa.w);
                uint2 b2f = make_uint2(qb.x, qb.y), b3f = make_uint2(qb.z, qb.w);
                mma_f16(o[0][nt], ah[0][0], b0);
                mma_f16(o[1][nt], ah[1][0], b0);
                mma_f16(o[0][nt], ah[0][1], b1f);
                mma_f16(o[1][nt], ah[1][1], b1f);
                mma_f16(o[0][nt], ah[0][2], b2f);
                mma_f16(o[1][nt], ah[1][2], b2f);
                mma_f16(o[0][nt], ah[0][3], b3f);
                mma_f16(o[1][nt], ah[1][3], b3f);
            }
        }

        // ---- epilogue: +b2, vectorized scatter-add ----------------------
        // sigma layout: blocks (2m, 2m+1) at tig cover cols [16m+4tig, +4):
        //   even row:  o[g2][2m][0], o[g2][2m][1], o[g2][2m+1][0], o[g2][2m+1][1]
        //   odd  row:  o[g2][2m][2], o[g2][2m][3], o[g2][2m+1][2], o[g2][2m+1][3]
        #pragma unroll
        for (int m = 0; m < 8; ++m) {
            int col = 16 * m + 4 * tig;
            float4 bb = *(const float4*)&b2s[col];
            #pragma unroll
            for (int g2 = 0; g2 < 2; ++g2) {
                int binE = bins[2 * g2], binO = bins[2 * g2 + 1];
                if (binE >= 0)
                    red_add4(out + (size_t)binE * OUT_DIM + col,
                             o[g2][2 * m][0] + bb.x, o[g2][2 * m][1] + bb.y,
                             o[g2][2 * m + 1][0] + bb.z, o[g2][2 * m + 1][1] + bb.w);
                if (binO >= 0)
                    red_add4(out + (size_t)binO * OUT_DIM + col,
                             o[g2][2 * m][2] + bb.x, o[g2][2 * m][3] + bb.y,
                             o[g2][2 * m + 1][2] + bb.z, o[g2][2 * m + 1][3] + bb.w);
            }
        }
    }
}

extern "C" void kernel_launch(void* const* d_in, const int* in_sizes, int n_in,
                              void* d_out, int out_size)
{
    const float* x     = (const float*)d_in[0];
    const int*   idx32 = (const int*)d_in[1];
    int wbase = 3;
    if (n_in >= 3 && in_sizes[2] == IN_DIM * HID_DIM) wbase = 2;
    const float* W1 = (const float*)d_in[wbase + 0];
    const float* b1 = (const float*)d_in[wbase + 1];
    const float* W2 = (const float*)d_in[wbase + 2];
    const float* b2 = (const float*)d_in[wbase + 3];
    float* out = (float*)d_out;

    const int n_items = in_sizes[0] / IN_DIM;
    const int n_tiles = (n_items + TM - 1) / TM;

    cudaFuncSetAttribute(item_encoder_mma,
                         cudaFuncAttributeMaxDynamicSharedMemorySize, SMEM_TOTAL);

    cudaMemsetAsync(d_out, 0, (size_t)out_size * sizeof(float), (cudaStream_t)0);

    const int prep_items = W1_QFRAGS + W2_QFRAGS;   // 6144
    prep_weights<<<prep_items / NTH, NTH, 0, (cudaStream_t)0>>>(W1, W2, idx32);

    item_encoder_mma<<<NSM, NTH, SMEM_TOTAL, (cudaStream_t)0>>>(
        x, idx32, b1, b2, out, n_items, n_tiles);
}

// round 16
// speedup vs baseline: 1.1769x; 1.0819x over previous
#include <cuda_runtime.h>
#include <cuda_fp16.h>
#include <cstdint>

#define IN_DIM   64
#define HID_DIM  256
#define OUT_DIM  128
#define TM       256          // items per CTA (32 rows per warp)
#define NTH      256
#define NSM      148

// paired-fragment arrays (uint4 = two adjacent-kt fp16 fragments per lane)
#define W1_QFRAGS (32 * 2 * 32)    // [jt=32][ktp=2][lane]
#define W2_QFRAGS (16 * 8 * 32)    // [nt=16][ktp=8][lane]

__device__ uint4 gW1[W1_QFRAGS];
__device__ uint4 gW2[W2_QFRAGS];
__device__ int g_idx_is_64;

// ---- smem byte offsets --------------------------------------------------
#define SMB_W1     0               // 32 KB
#define SMB_W2     32768           // 64 KB
#define SMB_B1H    98304           // 512 B (128 x half2)
#define SMB_B2     99328           // 512 B (128 x f32)
#define SMEM_TOTAL 99840

// ---- helpers ------------------------------------------------------------
__device__ __forceinline__ uint32_t pkhf(float lo, float hi) {   // low half = lo
    uint32_t r;
    asm("cvt.rn.f16x2.f32 %0, %1, %2;" : "=r"(r) : "f"(hi), "f"(lo));
    return r;
}
// fp32-accum mma (GEMM2). NOT volatile — ptxas schedules freely.
__device__ __forceinline__ void mma_f16(float* c, const uint32_t* a, uint2 b) {
    asm("mma.sync.aligned.m16n8k16.row.col.f32.f16.f16.f32 "
        "{%0,%1,%2,%3}, {%4,%5,%6,%7}, {%8,%9}, {%0,%1,%2,%3};"
        : "+f"(c[0]), "+f"(c[1]), "+f"(c[2]), "+f"(c[3])
        : "r"(a[0]), "r"(a[1]), "r"(a[2]), "r"(a[3]), "r"(b.x), "r"(b.y));
}
// fp16-accum mma (GEMM1): D/C are 2x fp16x2 regs = A-fragment layout.
__device__ __forceinline__ void mma_f16d(uint32_t* c, const uint32_t* a, uint2 b) {
    asm("mma.sync.aligned.m16n8k16.row.col.f16.f16.f16.f16 "
        "{%0,%1}, {%2,%3,%4,%5}, {%6,%7}, {%0,%1};"
        : "+r"(c[0]), "+r"(c[1])
        : "r"(a[0]), "r"(a[1]), "r"(a[2]), "r"(a[3]), "r"(b.x), "r"(b.y));
}
// half2 bias + relu, uint32-typed
__device__ __forceinline__ uint32_t hrelu2_add(uint32_t v, uint32_t b) {
    __half2 hv = *reinterpret_cast<__half2*>(&v);
    __half2 hb = *reinterpret_cast<__half2*>(&b);
    __half2 r = __hmax2(__hadd2(hv, hb), __float2half2_rn(0.f));
    return *reinterpret_cast<uint32_t*>(&r);
}
__device__ __forceinline__ void red_add4(float* p, float a, float b, float c, float d) {
    asm volatile("red.global.add.v4.f32 [%0], {%1, %2, %3, %4};"
                 :: "l"(p), "f"(a), "f"(b), "f"(c), "f"(d) : "memory");
}
__device__ __forceinline__ void prefetch_l2(const void* p) {
    asm volatile("prefetch.global.L2 [%0];" :: "l"(p));
}

// Output-column permutation for W2 fragments (validated R15):
// block nt = 2m+s, intra-block col j (0..7) -> physical col
//   sigma(nt, j) = 16*m + 4*(j>>1) + 2*s + (j&1)

// ---- prep: weights -> paired fp16 fragment layout (+ idx dtype probe) ---
__global__ void prep_weights(const float* __restrict__ W1,
                             const float* __restrict__ W2,
                             const int*   __restrict__ idx32) {
    if (blockIdx.x == 0 && threadIdx.x < 32) {
        int ok = (idx32[2 * threadIdx.x + 1] == 0);
        unsigned m = __ballot_sync(0xffffffffu, ok);
        if (threadIdx.x == 0) g_idx_is_64 = (m == 0xffffffffu);
    }

    int t = blockIdx.x * blockDim.x + threadIdx.x;
    if (t < W1_QFRAGS) {
        // [jt][ktp][lane]: uint4 = frag(kt=2*ktp) ++ frag(kt=2*ktp+1)
        int lane = t & 31, ktp = (t >> 5) & 1, jt = t >> 6;
        int n = jt * 8 + (lane >> 2), tg2 = (lane & 3) * 2;
        int ka = (2 * ktp) * 16 + tg2, kb = (2 * ktp + 1) * 16 + tg2;
        gW1[t] = make_uint4(
            pkhf(W1[ka * HID_DIM + n],       W1[(ka + 1) * HID_DIM + n]),
            pkhf(W1[(ka + 8) * HID_DIM + n], W1[(ka + 9) * HID_DIM + n]),
            pkhf(W1[kb * HID_DIM + n],       W1[(kb + 1) * HID_DIM + n]),
            pkhf(W1[(kb + 8) * HID_DIM + n], W1[(kb + 9) * HID_DIM + n]));
    } else if (t < W1_QFRAGS + W2_QFRAGS) {
        // [nt][ktp][lane], n permuted by sigma (see above)
        int u = t - W1_QFRAGS;
        int lane = u & 31, ktp = (u >> 5) & 7, nt = u >> 8;
        int j = lane >> 2;                       // intra-block col
        int m = nt >> 1, s = nt & 1;
        int n = 16 * m + 4 * (j >> 1) + 2 * s + (j & 1);
        int tg2 = (lane & 3) * 2;
        int ka = (2 * ktp) * 16 + tg2, kb = (2 * ktp + 1) * 16 + tg2;
        gW2[u] = make_uint4(
            pkhf(W2[ka * OUT_DIM + n],       W2[(ka + 1) * OUT_DIM + n]),
            pkhf(W2[(ka + 8) * OUT_DIM + n], W2[(ka + 9) * OUT_DIM + n]),
            pkhf(W2[kb * OUT_DIM + n],       W2[(kb + 1) * OUT_DIM + n]),
            pkhf(W2[(kb + 8) * OUT_DIM + n], W2[(kb + 9) * OUT_DIM + n]));
    }
}

// ---- main persistent fused kernel ---------------------------------------
__global__ __launch_bounds__(NTH, 1)
void item_encoder_mma(const float* __restrict__ x,
                      const int*   __restrict__ idx32,
                      const float* __restrict__ b1,
                      const float* __restrict__ b2,
                      float* __restrict__ out,
                      int n_items, int n_tiles)
{
    extern __shared__ char smc[];
    const uint4* sW1 = (const uint4*)(smc + SMB_W1);
    const uint4* sW2 = (const uint4*)(smc + SMB_W2);
    uint32_t* b1h = (uint32_t*)(smc + SMB_B1H);   // half2 per col-pair
    float* b2s = (float*)(smc + SMB_B2);

    const int tid = threadIdx.x;
    const int wid = tid >> 5, lane = tid & 31;
    const int gid = lane >> 2, tig = lane & 3;

    // ---- one-time prologue: stage weights + biases ----------------------
    {
        uint4* d = (uint4*)smc;
        const uint4* s1 = (const uint4*)gW1;
        const uint4* s2 = (const uint4*)gW2;
        #pragma unroll 4
        for (int i = tid; i < 2048; i += NTH) d[i] = s1[i];
        #pragma unroll 4
        for (int i = tid; i < 4096; i += NTH) d[2048 + i] = s2[i];
        if (tid < HID_DIM / 2) b1h[tid] = pkhf(b1[2 * tid], b1[2 * tid + 1]);
        if (tid < OUT_DIM) b2s[tid] = b2[tid];
    }
    __syncthreads();
    const int is64 = g_idx_is_64;
    const long long stride_items = (long long)gridDim.x * TM;

    // ---- persistent tile loop (no syncs inside) -------------------------
    for (int tile = blockIdx.x; tile < n_tiles; tile += gridDim.x) {
        const long long item0 = (long long)tile * TM;

        // L2 prefetch of next tile's x (two 128B lines per thread)
        {
            long long pfi = item0 + stride_items + (tid >> 1);
            if (pfi < n_items)
                prefetch_l2((const char*)(x + pfi * IN_DIM) + (tid & 1) * 128);
            pfi += 128;
            if (pfi < n_items)
                prefetch_l2((const char*)(x + pfi * IN_DIM) + (tid & 1) * 128);
        }

        // this warp's 4 rows: base + {0, 8, 16, 24}; groups g0={+0,+8}, g1={+16,+24}
        const long long rb = item0 + wid * 32 + gid;
        bool vok[4];
        #pragma unroll
        for (int g = 0; g < 4; ++g) vok[g] = (rb + 8 * g) < n_items;

        // ---- x fp16 A-fragments for both groups -------------------------
        uint32_t xh[2][4][4];
        #pragma unroll
        for (int g2 = 0; g2 < 2; ++g2) {
            const float* p0 = x + (rb + 16 * g2) * IN_DIM + tig * 2;
            const float* p1 = p0 + 8 * IN_DIM;
            #pragma unroll
            for (int kt = 0; kt < 4; ++kt) {
                float2 f0 = make_float2(0.f, 0.f), f1 = f0, f2 = f0, f3 = f0;
                if (vok[2 * g2])     { f0 = *(const float2*)(p0 + kt * 16);
                                       f2 = *(const float2*)(p0 + kt * 16 + 8); }
                if (vok[2 * g2 + 1]) { f1 = *(const float2*)(p1 + kt * 16);
                                       f3 = *(const float2*)(p1 + kt * 16 + 8); }
                xh[g2][kt][0] = pkhf(f0.x, f0.y);
                xh[g2][kt][1] = pkhf(f1.x, f1.y);
                xh[g2][kt][2] = pkhf(f2.x, f2.y);
                xh[g2][kt][3] = pkhf(f3.x, f3.y);
            }
        }
        // bins (direct gmem loads)
        int bins[4];
        #pragma unroll
        for (int g = 0; g < 4; ++g) {
            long long rr = rb + 8 * g;
            bins[g] = vok[g] ? (is64 ? (int)((const long long*)idx32)[rr]
                                     : idx32[rr])
                             : -1;
        }

        float o[2][16][4];
        #pragma unroll
        for (int g2 = 0; g2 < 2; ++g2)
            #pragma unroll
            for (int nt = 0; nt < 16; ++nt)
                #pragma unroll
                for (int q = 0; q < 4; ++q) o[g2][nt][q] = 0.f;

        // ---- 4 hidden chunks of 64 --------------------------------------
        #pragma unroll 1
        for (int c = 0; c < 4; ++c) {
            // GEMM1 (fp16 accum): D-regs ARE the GEMM2 A-fragments.
            uint32_t ah[2][4][4];
            #pragma unroll
            for (int j = 0; j < 8; ++j) {
                int fb = (c * 8 + j) * 2 * 32 + lane;
                uint4 qa = sW1[fb], qb = sW1[fb + 32];
                uint2 w0 = make_uint2(qa.x, qa.y), w1f = make_uint2(qa.z, qa.w);
                uint2 w2f = make_uint2(qb.x, qb.y), w3f = make_uint2(qb.z, qb.w);
                uint32_t bb = b1h[c * 32 + j * 4 + tig];
                int kt = j >> 1, s = (j & 1) * 2;

                uint32_t cc0[2] = {0u, 0u};
                uint32_t cc1[2] = {0u, 0u};
                mma_f16d(cc0, xh[0][0], w0);
                mma_f16d(cc1, xh[1][0], w0);
                mma_f16d(cc0, xh[0][1], w1f);
                mma_f16d(cc1, xh[1][1], w1f);
                mma_f16d(cc0, xh[0][2], w2f);
                mma_f16d(cc1, xh[1][2], w2f);
                mma_f16d(cc0, xh[0][3], w3f);
                mma_f16d(cc1, xh[1][3], w3f);

                ah[0][kt][s]     = hrelu2_add(cc0[0], bb);
                ah[0][kt][s + 1] = hrelu2_add(cc0[1], bb);
                ah[1][kt][s]     = hrelu2_add(cc1[0], bb);
                ah[1][kt][s + 1] = hrelu2_add(cc1[1], bb);
            }

            // GEMM2 (fp32 accum): each W2 fragment pair feeds both groups
            #pragma unroll
            for (int nt = 0; nt < 16; ++nt) {
                int fb = (nt * 8 + c * 2) * 32 + lane;
                uint4 qa = sW2[fb], qb = sW2[fb + 32];
                uint2 b0 = make_uint2(qa.x, qa.y), b1f = make_uint2(qa.z, qa.w);
                uint2 b2f = make_uint2(qb.x, qb.y), b3f = make_uint2(qb.z, qb.w);
                mma_f16(o[0][nt], ah[0][0], b0);
                mma_f16(o[1][nt], ah[1][0], b0);
                mma_f16(o[0][nt], ah[0][1], b1f);
                mma_f16(o[1][nt], ah[1][1], b1f);
                mma_f16(o[0][nt], ah[0][2], b2f);
                mma_f16(o[1][nt], ah[1][2], b2f);
                mma_f16(o[0][nt], ah[0][3], b3f);
                mma_f16(o[1][nt], ah[1][3], b3f);
            }
        }

        // ---- epilogue: +b2, vectorized scatter-add (sigma layout) -------
        #pragma unroll
        for (int m = 0; m < 8; ++m) {
            int col = 16 * m + 4 * tig;
            float4 bb = *(const float4*)&b2s[col];
            #pragma unroll
            for (int g2 = 0; g2 < 2; ++g2) {
                int binE = bins[2 * g2], binO = bins[2 * g2 + 1];
                if (binE >= 0)
                    red_add4(out + (size_t)binE * OUT_DIM + col,
                             o[g2][2 * m][0] + bb.x, o[g2][2 * m][1] + bb.y,
                             o[g2][2 * m + 1][0] + bb.z, o[g2][2 * m + 1][1] + bb.w);
                if (binO >= 0)
                    red_add4(out + (size_t)binO * OUT_DIM + col,
                             o[g2][2 * m][2] + bb.x, o[g2][2 * m][3] + bb.y,
                             o[g2][2 * m + 1][2] + bb.z, o[g2][2 * m + 1][3] + bb.w);
            }
        }
    }
}

extern "C" void kernel_launch(void* const* d_in, const int* in_sizes, int n_in,
                              void* d_out, int out_size)
{
    const float* x     = (const float*)d_in[0];
    const int*   idx32 = (const int*)d_in[1];
    int wbase = 3;
    if (n_in >= 3 && in_sizes[2] == IN_DIM * HID_DIM) wbase = 2;
    const float* W1 = (const float*)d_in[wbase + 0];
    const float* b1 = (const float*)d_in[wbase + 1];
    const float* W2 = (const float*)d_in[wbase + 2];
    const float* b2 = (const float*)d_in[wbase + 3];
    float* out = (float*)d_out;

    const int n_items = in_sizes[0] / IN_DIM;
    const int n_tiles = (n_items + TM - 1) / TM;

    cudaFuncSetAttribute(item_encoder_mma,
                         cudaFuncAttributeMaxDynamicSharedMemorySize, SMEM_TOTAL);

    cudaMemsetAsync(d_out, 0, (size_t)out_size * sizeof(float), (cudaStream_t)0);

    const int prep_items = W1_QFRAGS + W2_QFRAGS;   // 6144
    prep_weights<<<prep_items / NTH, NTH, 0, (cudaStream_t)0>>>(W1, W2, idx32);

    item_encoder_mma<<<NSM, NTH, SMEM_TOTAL, (cudaStream_t)0>>>(
        x, idx32, b1, b2, out, n_items, n_tiles);
}